// round 13
// baseline (speedup 1.0000x reference)
#include <cuda_runtime.h>
#include <cstdint>

// Problem constants (from reference)
#define SEQ    4096
#define CIN    7
#define NK     586        // 585 regular kernels + 1 "last"
#define GLEN   12288      // SEQ * KW(3)
#define HP     12289      // output positions per channel-kernel row
#define GPITCH 12304      // GLEN + 16, keeps 16B alignment
#define CTOT   4096       // 7*585 + 1
#define NCP    2048       // c-pairs
#define HTILE  30         // 3 ring cycles of 10 rows

typedef unsigned long long u64;

// Scratch (allocation-free rule: __device__ globals). +16 slack u64s for window overreads.
__device__ u64   g_Gdup[CIN * GPITCH + 16]; // duplicated signal: (g,g) f32x2, g[i]=g_ch[i-4]
__device__ float g_Wmid[NK * 8];            // middle column of each 8x3 kernel (slow path)
__device__ u64   g_WpkT[8 * NCP];           // TRANSPOSED packed weights: [tap][cpair]

__device__ __forceinline__ u64 pk2(float lo, float hi) {
    u64 r; asm("mov.b64 %0, {%1,%2};" : "=l"(r) : "f"(lo), "f"(hi)); return r;
}
__device__ __forceinline__ u64 fma2(u64 a, u64 b, u64 c) {
    u64 d; asm("fma.rn.f32x2 %0, %1, %2, %3;" : "=l"(d) : "l"(a), "l"(b), "l"(c)); return d;
}

// ---- fused prep: mid-column weights, transposed packed weight pairs, duplicated signal ----
__global__ void prep(const float* __restrict__ x, const float* __restrict__ kernels) {
    int idx = blockIdx.x * blockDim.x + threadIdx.x;
    if (idx < NK * 8) {
        int k = idx >> 3, a = idx & 7;
        g_Wmid[idx] = kernels[k * 24 + a * 3 + 1];
    }
    if (idx < 8 * NCP) {
        int a = idx / NCP, cp = idx - a * NCP;
        int c0 = 2 * cp, c1 = c0 + 1;
        int k0 = (c0 == CTOT - 1) ? 585 : (c0 % 585);
        int k1 = (c1 == CTOT - 1) ? 585 : (c1 % 585);
        g_WpkT[idx] = pk2(kernels[k0 * 24 + a * 3 + 1], kernels[k1 * 24 + a * 3 + 1]);
    }
    if (idx < CIN * GPITCH) {
        int ch = idx / GPITCH;
        int i  = idx - ch * GPITCH;
        int t  = i - 4;
        float v = 0.f;
        if (t >= 0 && t < GLEN) {
            int s = t / 3;
            int j = t - s * 3;
            int src = s + j;
            if (src > SEQ - 1) src = SEQ - 1;
            v = x[src * CIN + ch];
        }
        g_Gdup[idx] = pk2(v, v);
    }
}

// One 2-row phase on a mod-10 ring: all indices compile-time -> zero shift MOVs.
// After computing rows 2p,2p+1 of this 10-row cycle, refill two slots with one LDG.128.
#define PHASE(p) do {                                                          \
    _Pragma("unroll")                                                          \
    for (int u = 0; u < 2; u++) {                                              \
        u64 acc = 0ull;                                                        \
        _Pragma("unroll")                                                      \
        for (int a = 0; a < 8; a++)                                            \
            acc = fma2(P[(2*(p) + u + a) % 10], W[a], acc);                    \
        *(u64*)op = acc;                                                       \
        op += CTOT * sizeof(float);                                            \
    }                                                                          \
    {                                                                          \
        ulonglong2 nv = *(const ulonglong2*)(gp + base + 2*(p) + 10);          \
        P[(2*(p))     % 10] = nv.x;                                            \
        P[(2*(p) + 1) % 10] = nv.y;                                            \
    }                                                                          \
} while (0)

// ---- main kernel: one c-pair per thread, 30 rows per tile, STG.64 per row,
//      SoA weights, pre-duplicated g, mod-10 ring, 48-reg cap -> 5 CTAs/SM ----
__global__ void __launch_bounds__(256, 5) conv_main(float* __restrict__ out) {
    const int tid = threadIdx.x;
    const int cp  = blockIdx.x * 256 + tid;     // [0, 2048), grid.x = 8
    const int c0  = cp * 2;
    const int h0  = blockIdx.y * HTILE;

    const int ch0 = c0 / 585;                   // c0 even -> never the special 4095
    const int c1  = c0 + 1;
    const int ch1 = (c1 == CTOT - 1) ? 0 : c1 / 585;

    const bool uniform  = (ch0 == ch1);
    const bool fulltile = (h0 + HTILE <= HP);

    if (uniform && fulltile) {
        // 8 packed weight pairs, warp-contiguous SoA loads
        u64 W[8];
#pragma unroll
        for (int a = 0; a < 8; a++) W[a] = g_WpkT[a * NCP + cp];

        const u64* __restrict__ gp = &g_Gdup[ch0 * GPITCH + h0];   // 16B-aligned (h0 even)

        // Ring init: values 0..9 (5 x LDG.128)
        u64 P[10];
        {
            ulonglong2 t0 = *(const ulonglong2*)(gp);
            ulonglong2 t1 = *(const ulonglong2*)(gp + 2);
            ulonglong2 t2 = *(const ulonglong2*)(gp + 4);
            ulonglong2 t3 = *(const ulonglong2*)(gp + 6);
            ulonglong2 t4 = *(const ulonglong2*)(gp + 8);
            P[0] = t0.x; P[1] = t0.y; P[2] = t1.x; P[3] = t1.y;
            P[4] = t2.x; P[5] = t2.y; P[6] = t3.x; P[7] = t3.y;
            P[8] = t4.x; P[9] = t4.y;
        }

        char* op = (char*)(out + (size_t)h0 * CTOT + c0);
#pragma unroll
        for (int cyc = 0; cyc < HTILE / 10; cyc++) {
            const int base = cyc * 10;
            PHASE(0); PHASE(1); PHASE(2); PHASE(3); PHASE(4);
        }
    } else {
        // Slow path: channel-crossing pairs (4 of 2048) and the 19-row tail tile.
        int kk0 = (c0 == CTOT - 1) ? 585 : c0 % 585;
        int kk1 = (c1 == CTOT - 1) ? 585 : c1 % 585;
        float w0[8], w1[8];
#pragma unroll
        for (int a = 0; a < 8; a++) {
            w0[a] = g_Wmid[kk0 * 8 + a];
            w1[a] = g_Wmid[kk1 * 8 + a];
        }
        int hEnd = min(h0 + HTILE, HP);
        for (int h = h0; h < hEnd; h++) {
            const float* ga = (const float*)&g_Gdup[ch0 * GPITCH + h];
            const float* gb = (const float*)&g_Gdup[ch1 * GPITCH + h];
            float s0 = 0.f, s1 = 0.f;
#pragma unroll
            for (int a = 0; a < 8; a++) {
                s0 = fmaf(ga[2 * a], w0[a], s0);
                s1 = fmaf(gb[2 * a], w1[a], s1);
            }
            float2 o; o.x = s0; o.y = s1;
            *(float2*)&out[(size_t)h * CTOT + c0] = o;
        }
    }
}

extern "C" void kernel_launch(void* const* d_in, const int* in_sizes, int n_in,
                              void* d_out, int out_size) {
    const float* x       = (const float*)d_in[0];
    const float* kernels = (const float*)d_in[1];
    if (n_in >= 2 && in_sizes[0] == NK * 24) {   // defensive: swapped order
        kernels = (const float*)d_in[0];
        x       = (const float*)d_in[1];
    }
    float* out = (float*)d_out;

    prep<<<(CIN * GPITCH + 255) / 256, 256>>>(x, kernels);

    dim3 grid(NCP / 256, (HP + HTILE - 1) / HTILE);  // (8, 410) = 3280 CTAs
    conv_main<<<grid, 256>>>(out);
}

// round 14
// speedup vs baseline: 1.1729x; 1.1729x over previous
#include <cuda_runtime.h>
#include <cstdint>

// Problem constants (from reference)
#define SEQ    4096
#define CIN    7
#define NK     586        // 585 regular kernels + 1 "last"
#define GLEN   12288      // SEQ * KW(3)
#define HP     12289      // output positions per channel-kernel row
#define CTOT   4096       // 7*585 + 1
#define NCP    2048       // c-pairs
#define HTILE  36         // 3 ring cycles of 12 rows
#define WWIN   48         // staged window slots per channel (covers ring overreads)

typedef unsigned long long u64;

// Scratch (allocation-free rule: __device__ globals)
__device__ float g_Wmid[NK * 8];    // middle column of each 8x3 kernel (slow path)
__device__ u64   g_WpkT[8 * NCP];   // TRANSPOSED packed weights: [tap][cpair]

__device__ __forceinline__ u64 pk2(float lo, float hi) {
    u64 r; asm("mov.b64 %0, {%1,%2};" : "=l"(r) : "f"(lo), "f"(hi)); return r;
}
__device__ __forceinline__ u64 fma2(u64 a, u64 b, u64 c) {
    u64 d; asm("fma.rn.f32x2 %0, %1, %2, %3;" : "=l"(d) : "l"(a), "l"(b), "l"(c)); return d;
}
__device__ __forceinline__ void stcs64(void* p, u64 v) {
    asm volatile("st.global.cs.b64 [%0], %1;" :: "l"(p), "l"(v) : "memory");
}

// ---- prep: weights only (64 blocks) ----
__global__ void prep(const float* __restrict__ kernels) {
    int idx = blockIdx.x * blockDim.x + threadIdx.x;
    if (idx < NK * 8) {
        int k = idx >> 3, a = idx & 7;
        g_Wmid[idx] = kernels[k * 24 + a * 3 + 1];
    }
    if (idx < 8 * NCP) {
        int a = idx / NCP, cp = idx - a * NCP;
        int c0 = 2 * cp, c1 = c0 + 1;
        int k0 = (c0 == CTOT - 1) ? 585 : (c0 % 585);
        int k1 = (c1 == CTOT - 1) ? 585 : (c1 % 585);
        g_WpkT[idx] = pk2(kernels[k0 * 24 + a * 3 + 1], kernels[k1 * 24 + a * 3 + 1]);
    }
}

// Gather one signal value: g_ch[t] with edge clamping; 0 outside [0, GLEN)
__device__ __forceinline__ float gatherg(const float* __restrict__ x, int ch, int t) {
    if (t < 0 || t >= GLEN) return 0.f;
    int s = t / 3;
    int j = t - s * 3;
    int src = s + j;
    if (src > SEQ - 1) src = SEQ - 1;
    return x[src * CIN + ch];
}

// One 4-row phase on the mod-12 ring: all indices compile-time -> zero shift MOVs.
// Refill comes from the SHARED window (LDS.128, broadcast).
#define PHASE(p) do {                                                          \
    _Pragma("unroll")                                                          \
    for (int u = 0; u < 4; u++) {                                              \
        u64 acc = 0ull;                                                        \
        _Pragma("unroll")                                                      \
        for (int a = 0; a < 8; a++)                                            \
            acc = fma2(P[(4*(p) + u + a) % 12], W[a], acc);                    \
        stcs64(op, acc);                                                       \
        op += CTOT * sizeof(float);                                            \
    }                                                                          \
    {                                                                          \
        ulonglong2 nv0 = *(const ulonglong2*)(gp + base + 4*(p) + 12);         \
        ulonglong2 nv1 = *(const ulonglong2*)(gp + base + 4*(p) + 14);         \
        P[(4*(p))     % 12] = nv0.x;                                           \
        P[(4*(p) + 1) % 12] = nv0.y;                                           \
        P[(4*(p) + 2) % 12] = nv1.x;                                           \
        P[(4*(p) + 3) % 12] = nv1.y;                                           \
    }                                                                          \
} while (0)

// ---- main kernel: smem-staged window, mod-12 ring, STG.64 streaming stores ----
__global__ void __launch_bounds__(256, 4) conv_main(const float* __restrict__ x,
                                                    float* __restrict__ out) {
    const int tid = threadIdx.x;
    const int bx  = blockIdx.x;                 // [0, 8)
    const int cp  = bx * 256 + tid;             // [0, 2048)
    const int c0  = cp * 2;
    const int h0  = blockIdx.y * HTILE;

    // Channels present in this CTA's c-range [bx*512, bx*512+512)
    const int chA = (bx * 512) / 585;
    const int chBw = (bx == 7) ? 0 : (bx * 512 + 511) / 585;   // window-1 channel

    __shared__ __align__(16) u64 win[2][WWIN];  // duplicated (g,g) pairs

    // Stage both channel windows (96 slots by first 96 threads), values for
    // t = h0 + idx - 4 .. covers ring reads up to h0+47.
    if (tid < 2 * WWIN) {
        int which = tid / WWIN;
        int idx   = tid - which * WWIN;
        int ch    = which ? chBw : chA;
        float v   = gatherg(x, ch, h0 + idx - 4);
        win[which][idx] = pk2(v, v);
    }
    __syncthreads();

    const int ch0 = c0 / 585;                   // c0 even -> never the special 4095
    const int c1  = c0 + 1;
    const int ch1 = (c1 == CTOT - 1) ? 0 : c1 / 585;

    const bool uniform  = (ch0 == ch1);
    const bool fulltile = (h0 + HTILE <= HP);

    if (uniform && fulltile) {
        // 8 packed weight pairs, warp-contiguous SoA loads
        u64 W[8];
#pragma unroll
        for (int a = 0; a < 8; a++) W[a] = g_WpkT[a * NCP + cp];

        const u64* gp = (ch0 == chA) ? win[0] : win[1];   // shared-memory window

        // Ring init: values 0..11 (6 x LDS.128, broadcast)
        u64 P[12];
        {
            ulonglong2 t0 = *(const ulonglong2*)(gp);
            ulonglong2 t1 = *(const ulonglong2*)(gp + 2);
            ulonglong2 t2 = *(const ulonglong2*)(gp + 4);
            ulonglong2 t3 = *(const ulonglong2*)(gp + 6);
            ulonglong2 t4 = *(const ulonglong2*)(gp + 8);
            ulonglong2 t5 = *(const ulonglong2*)(gp + 10);
            P[0] = t0.x; P[1] = t0.y; P[2]  = t1.x; P[3]  = t1.y;
            P[4] = t2.x; P[5] = t2.y; P[6]  = t3.x; P[7]  = t3.y;
            P[8] = t4.x; P[9] = t4.y; P[10] = t5.x; P[11] = t5.y;
        }

        char* op = (char*)(out + (size_t)h0 * CTOT + c0);
#pragma unroll
        for (int cyc = 0; cyc < HTILE / 12; cyc++) {
            const int base = cyc * 12;
            PHASE(0); PHASE(1); PHASE(2);
        }
    } else {
        // Slow path: channel-crossing pairs (4 of 2048) and the 13-row tail tile.
        int kk0 = (c0 == CTOT - 1) ? 585 : c0 % 585;
        int kk1 = (c1 == CTOT - 1) ? 585 : c1 % 585;
        float w0[8], w1[8];
#pragma unroll
        for (int a = 0; a < 8; a++) {
            w0[a] = g_Wmid[kk0 * 8 + a];
            w1[a] = g_Wmid[kk1 * 8 + a];
        }
        const float* ga = (const float*)((ch0 == chA) ? win[0] : win[1]);
        const float* gb = (const float*)((ch1 == chA) ? win[0] : win[1]);
        int hEnd = min(h0 + HTILE, HP);
        for (int h = h0; h < hEnd; h++) {
            int r = h - h0;
            float s0 = 0.f, s1 = 0.f;
#pragma unroll
            for (int a = 0; a < 8; a++) {
                s0 = fmaf(ga[2 * (r + a)], w0[a], s0);
                s1 = fmaf(gb[2 * (r + a)], w1[a], s1);
            }
            float2 o; o.x = s0; o.y = s1;
            *(float2*)&out[(size_t)h * CTOT + c0] = o;
        }
    }
}

extern "C" void kernel_launch(void* const* d_in, const int* in_sizes, int n_in,
                              void* d_out, int out_size) {
    const float* x       = (const float*)d_in[0];
    const float* kernels = (const float*)d_in[1];
    if (n_in >= 2 && in_sizes[0] == NK * 24) {   // defensive: swapped order
        kernels = (const float*)d_in[0];
        x       = (const float*)d_in[1];
    }
    float* out = (float*)d_out;

    prep<<<64, 256>>>(kernels);

    dim3 grid(NCP / 256, (HP + HTILE - 1) / HTILE);  // (8, 342)
    conv_main<<<grid, 256>>>(x, out);
}